// round 11
// baseline (speedup 1.0000x reference)
#include <cuda_runtime.h>
#include <cuda_bf16.h>
#include <cstdint>

typedef unsigned long long u64;
typedef uint32_t u32;
typedef unsigned short u16;
typedef unsigned char u8;

#define DEV_INLINE __device__ __forceinline__

// ------------------------- constants -------------------------
static constexpr int B_ = 4;
static constexpr int C_ = 256;
static constexpr int D_ = 32;     // C/8
static constexpr int N_ = 4096;   // 64*64
static constexpr int BI = 64;     // queries per CTA
static constexpr int BJ = 256;    // keys per j-tile
static constexpr int NT = N_ / BJ; // 16 tiles

// exp scale: 1/sqrt(C) folded into exp2 argument (Q stored UNSCALED for e4m3 range)
#define EXP_SCL 0.09016843980556022f   // log2(e)/16

// fp8 scratch (static device globals — allocation-free per harness rules)
__device__ __align__(16) u8 g_Qt8[B_ * N_ * 32];   // [b][n][32d] e4m3, 32B rows
__device__ __align__(16) u8 g_Kt8[B_ * N_ * 32];   // [b][n][32d]
__device__ __align__(16) u8 g_V8 [B_ * C_ * N_];   // [b][c][n]  e4m3

// ------------------------- helpers -------------------------
DEV_INLINE u32 smem_u32(const void* p) {
    u32 a; asm("{ .reg .u64 t; cvta.to.shared.u64 t, %1; cvt.u32.u64 %0, t; }" : "=r"(a) : "l"(p));
    return a;
}
DEV_INLINE u64 pk2(float a, float b) { u64 r; asm("mov.b64 %0, {%1,%2};" : "=l"(r) : "f"(a), "f"(b)); return r; }
DEV_INLINE void upk2(u64 v, float& a, float& b) { asm("mov.b64 {%0,%1}, %2;" : "=f"(a), "=f"(b) : "l"(v)); }
DEV_INLINE void fma2(u64& d, u64 a, u64 b) { asm("fma.rn.f32x2 %0, %1, %2, %0;" : "+l"(d) : "l"(a), "l"(b)); }

DEV_INLINE void ldsm4(u32& r0, u32& r1, u32& r2, u32& r3, u32 addr) {
    asm volatile("ldmatrix.sync.aligned.m8n8.x4.shared.b16 {%0,%1,%2,%3}, [%4];"
                 : "=r"(r0), "=r"(r1), "=r"(r2), "=r"(r3) : "r"(addr));
}
// fp8 e4m3 mma: D(f32) = A(16x32 e4m3) * B(8x32 e4m3)^T + D
DEV_INLINE void mmafp8(float* c, const u32* a, u32 b0, u32 b1) {
    asm volatile(
        "mma.sync.aligned.m16n8k32.row.col.f32.e4m3.e4m3.f32 "
        "{%0,%1,%2,%3}, {%4,%5,%6,%7}, {%8,%9}, {%0,%1,%2,%3};"
        : "+f"(c[0]), "+f"(c[1]), "+f"(c[2]), "+f"(c[3])
        : "r"(a[0]), "r"(a[1]), "r"(a[2]), "r"(a[3]), "r"(b0), "r"(b1));
}
DEV_INLINE u16 e4m3x2(float hi, float lo) {
    u16 r; asm("cvt.rn.satfinite.e4m3x2.f32 %0, %1, %2;" : "=h"(r) : "f"(hi), "f"(lo)); return r;
}
DEV_INLINE float ex2f(float s) {
    float e; asm("ex2.approx.ftz.f32 %0, %1;" : "=f"(e) : "f"(s)); return e;
}
DEV_INLINE void cpa16(u32 dst, const void* src) {
    asm volatile("cp.async.cg.shared.global [%0], [%1], 16;" :: "r"(dst), "l"(src));
}
#define CP_COMMIT() asm volatile("cp.async.commit_group;" ::: "memory")
#define CP_WAIT(n)  asm volatile("cp.async.wait_group %0;" :: "n"(n) : "memory")

// Q/K tiles: 32B rows (32 e4m3 of d); 16B chunk ^= row>>2
DEV_INLINE u32 kswz(int row, int c) { return (u32)(row * 32 + (((c ^ (row >> 2)) & 1) << 4)); }
// V/P tiles: 256B rows; 16B chunk ^= row&7
DEV_INLINE u32 vswz(int row, int ch) { return (u32)(row * 256 + ((ch ^ (row & 7)) << 4)); }

// attn SMEM layout (dynamic, bytes)
static constexpr int SM_P1  = 0;
static constexpr int SM_Q   = 0;
static constexpr int SM_P0  = 16384;
static constexpr int SM_K0  = 32768;
static constexpr int SM_K1  = 40960;
static constexpr int SM_V   = 49152;
static constexpr int SM_L   = 114688;
static constexpr int SM_INV = 115200;
static constexpr int SMEM_SZ = 115456;

// proj SMEM: Ws f32[256][34] + 2 x-chunk buffers [16ch][256n] f32
static constexpr int PSM_WS  = 0;            // 34816 B
static constexpr int PSM_X0  = 34816;        // 16384 B
static constexpr int PSM_X1  = 51200;        // 16384 B
static constexpr int PSMEM_SZ = 67584;       // 66 KB -> 3 CTAs/SM

// ------------------------- unified projection kernel -------------------------
// grid (N/256, 10, B): y<8 -> V rows y*32; y==8 -> Q; y==9 -> K.
// One n per thread; x staged via cp.async double-buffered 16-channel chunks.
__global__ __launch_bounds__(256, 3) void proj_kernel(
    const float* __restrict__ x,
    const float* __restrict__ Wq, const float* __restrict__ bq,
    const float* __restrict__ Wk, const float* __restrict__ bk,
    const float* __restrict__ Wv, const float* __restrict__ bv)
{
    extern __shared__ __align__(16) char psm[];
    const u32 psb = smem_u32(psm);
    float* Ws = (float*)(psm + PSM_WS);
    const u32 xbuf[2] = { psb + PSM_X0, psb + PSM_X1 };

    const int tid = threadIdx.x;
    const int nbase = blockIdx.x * 256;
    const int n0 = nbase + tid;
    const int y  = blockIdx.y;
    const int b  = blockIdx.z;

    const float* W; const float* bias; int r0; int mode;
    if (y < 8)       { W = Wv; bias = bv; r0 = y * 32; mode = 0; }
    else if (y == 8) { W = Wq; bias = bq; r0 = 0;      mode = 1; }
    else             { W = Wk; bias = bk; r0 = 0;      mode = 2; }

    for (int idx = tid; idx < 32 * 256; idx += 256) {
        int r = idx >> 8, c = idx & 255;
        Ws[c * 34 + r] = W[(r0 + r) * 256 + c];
    }

    const char* xb = (const char*)(x + ((size_t)b * C_) * N_ + nbase);
    {
#pragma unroll
        for (int it = 0; it < 4; it++) {
            int idx = tid + it * 256;
            int row = idx >> 6, off = (idx & 63) << 4;
            cpa16(xbuf[0] + row * 1024 + off, xb + (size_t)row * (N_ * 4) + off);
        }
        CP_COMMIT();
    }

    u64 accA[16];
#pragma unroll
    for (int k = 0; k < 16; k++) accA[k] = 0ull;

#pragma unroll 1
    for (int ch = 0; ch < 16; ch++) {
        if (ch < 15) {
            const int c1 = (ch + 1) * 16;
#pragma unroll
            for (int it = 0; it < 4; it++) {
                int idx = tid + it * 256;
                int row = idx >> 6, off = (idx & 63) << 4;
                cpa16(xbuf[(ch + 1) & 1] + row * 1024 + off,
                      xb + (size_t)(c1 + row) * (N_ * 4) + off);
            }
            CP_COMMIT();
            CP_WAIT(1);
        } else {
            CP_WAIT(0);
        }
        __syncthreads();

        const char* xs = (const char*)psm + (xbuf[ch & 1] - psb);
#pragma unroll
        for (int cc = 0; cc < 16; cc++) {
            const int c = ch * 16 + cc;
            float v = *(const float*)(xs + cc * 1024 + tid * 4);
            u64 a2 = pk2(v, v);
            const u64* wrow = (const u64*)&Ws[c * 34];
#pragma unroll
            for (int k = 0; k < 16; k++) fma2(accA[k], wrow[k], a2);
        }
        __syncthreads();
    }

    if (mode == 0) {
        u8* ob = g_V8 + ((size_t)b * C_ + r0) * N_ + n0;
#pragma unroll
        for (int k = 0; k < 16; k++) {
            float lo, hi; upk2(accA[k], lo, hi);
            u16 w0 = e4m3x2(0.0f, lo + bias[r0 + 2 * k]);
            u16 w1 = e4m3x2(0.0f, hi + bias[r0 + 2 * k + 1]);
            ob[(size_t)(2 * k) * N_]     = (u8)w0;
            ob[(size_t)(2 * k + 1) * N_] = (u8)w1;
        }
    } else {
        u8* base = (mode == 1) ? g_Qt8 : g_Kt8;
        u32 h[8];
#pragma unroll
        for (int j = 0; j < 8; j++) {
            float l0, h0, l1, h1;
            upk2(accA[2 * j], l0, h0); upk2(accA[2 * j + 1], l1, h1);
            u16 wa = e4m3x2(h0 + bias[4 * j + 1], l0 + bias[4 * j]);
            u16 wb = e4m3x2(h1 + bias[4 * j + 3], l1 + bias[4 * j + 2]);
            h[j] = (u32)wa | ((u32)wb << 16);
        }
        uint4* op = (uint4*)(base + ((size_t)b * N_ + n0) * 32);
        op[0] = make_uint4(h[0], h[1], h[2], h[3]);
        op[1] = make_uint4(h[4], h[5], h[6], h[7]);
    }
}

// ------------------------- attention device helpers -------------------------
struct AttnCtx {
    u32 sb; int tid, lane, warp, rr, mat, mr, jb, cb;
};

// S = Q.K^T (warp: 16q x 128j), exp, e4m3 P write, l accumulate
DEV_INLINE void s_phase(const AttnCtx& cx, char* smem, u32 kbuf, u32 pofs,
                        const u32 aq[4], float& lacc0, float& lacc1)
{
    const int q0 = cx.mr + (cx.lane >> 2);
    const int jl = 2 * (cx.lane & 3);
    const u32 prow0 = pofs + q0 * 256 + ((q0 & 7) << 4);
    const u32 prow8 = prow0 + 8 * 256;
#pragma unroll
    for (int nbp = 0; nbp < 8; nbp++) {
        const int jcol = cx.jb + nbp * 16;
        const int rowB = jcol + ((cx.mat >> 1) << 3) + cx.rr;
        u32 b0, b1, b2, b3;
        ldsm4(b0, b1, b2, b3, kbuf + kswz(rowB, cx.mat & 1));
        float s[8] = {0.f,0.f,0.f,0.f,0.f,0.f,0.f,0.f};
        mmafp8(&s[0], aq, b0, b1);
        mmafp8(&s[4], aq, b2, b3);
        float e0 = ex2f(s[0] * EXP_SCL), e1 = ex2f(s[1] * EXP_SCL);
        float e2 = ex2f(s[2] * EXP_SCL), e3 = ex2f(s[3] * EXP_SCL);
        float e4 = ex2f(s[4] * EXP_SCL), e5 = ex2f(s[5] * EXP_SCL);
        float e6 = ex2f(s[6] * EXP_SCL), e7 = ex2f(s[7] * EXP_SCL);
        lacc0 += (e0 + e1) + (e4 + e5);
        lacc1 += (e2 + e3) + (e6 + e7);
        const u32 csw = (u32)(((jcol >> 4) ^ (q0 & 7)) << 4) - (u32)((q0 & 7) << 4);
        *(u16*)(smem + prow0 + csw + jl)     = e4m3x2(e1, e0);
        *(u16*)(smem + prow0 + csw + jl + 8) = e4m3x2(e5, e4);
        *(u16*)(smem + prow8 + csw + jl)     = e4m3x2(e3, e2);
        *(u16*)(smem + prow8 + csw + jl + 8) = e4m3x2(e7, e6);
    }
}

// O += P.V^T (warp: 64q x 32c, K = 256 j)
DEV_INLINE void pv_phase(const AttnCtx& cx, u32 pbuf, u32 vbuf, float pv[64])
{
#pragma unroll
    for (int kk = 0; kk < 8; kk++) {
        u32 ap[4][4];
#pragma unroll
        for (int mt = 0; mt < 4; mt++) {
            const int rowA = mt * 16 + ((cx.mat & 1) << 3) + cx.rr;
            ldsm4(ap[mt][0], ap[mt][1], ap[mt][2], ap[mt][3],
                  pbuf + vswz(rowA, kk * 2 + (cx.mat >> 1)));
        }
#pragma unroll
        for (int np = 0; np < 2; np++) {
            const int rowV = cx.cb + np * 16 + ((cx.mat >> 1) << 3) + cx.rr;
            u32 b0, b1, b2, b3;
            ldsm4(b0, b1, b2, b3, vbuf + vswz(rowV, kk * 2 + (cx.mat & 1)));
#pragma unroll
            for (int mt = 0; mt < 4; mt++) {
                mmafp8(&pv[(mt * 4 + np * 2) * 4],     ap[mt], b0, b1);
                mmafp8(&pv[(mt * 4 + np * 2 + 1) * 4], ap[mt], b2, b3);
            }
        }
    }
}

DEV_INLINE void stage_K(const AttnCtx& cx, u32 kbuf, const u8* Ktb, int j0) {
#pragma unroll
    for (int it = 0; it < 2; it++) {
        int idx = cx.tid + it * 256;
        int row = idx >> 1, c = idx & 1;
        cpa16(kbuf + kswz(row, c), Ktb + (size_t)(j0 + row) * 32 + c * 16);
    }
}
DEV_INLINE void stage_V(const AttnCtx& cx, u32 vbuf, const u8* Vb, int j0) {
#pragma unroll
    for (int it = 0; it < 16; it++) {
        int idx = cx.tid + it * 256;
        int row = idx >> 4, ch = idx & 15;
        cpa16(vbuf + vswz(row, ch), Vb + (size_t)row * N_ + j0 + ch * 16);
    }
}

// ------------------------- attention kernel -------------------------
// grid (N/64, B), 256 threads (8 warps), 2 CTAs/SM, fp8 operands.
// Skewed pipeline: iter t computes S(t) then PV(t-1). NT=16 tiles of 256 j.
__global__ __launch_bounds__(256, 2) void attn_kernel(
    const float* __restrict__ x, const float* __restrict__ gamma,
    float* __restrict__ out)
{
    extern __shared__ __align__(1024) char smem[];
    AttnCtx cx;
    cx.sb = smem_u32(smem);
    cx.tid = threadIdx.x;
    cx.lane = cx.tid & 31;
    cx.warp = cx.tid >> 5;
    cx.rr = cx.lane & 7;
    cx.mat = cx.lane >> 3;
    cx.mr = (cx.warp >> 1) * 16;
    cx.jb = (cx.warp & 1) * 128;
    cx.cb = cx.warp * 32;
    const int jh = cx.warp & 1;
    const int i0 = blockIdx.x * BI;
    const int b  = blockIdx.y;

    const u8* Qtb = g_Qt8 + (size_t)b * N_ * 32;
    const u8* Ktb = g_Kt8 + (size_t)b * N_ * 32;
    const u8* Vb  = g_V8  + (size_t)b * C_ * N_;

    // ---- pre-loop staging: {Q, K0} group, {V0} group ----
    {
        if (cx.tid < 128) {
            int row = cx.tid >> 1, c = cx.tid & 1;
            cpa16(cx.sb + SM_Q + kswz(row, c), Qtb + (size_t)(i0 + row) * 32 + c * 16);
        }
        stage_K(cx, cx.sb + SM_K0, Ktb, 0);
        CP_COMMIT();
        stage_V(cx, cx.sb + SM_V, Vb, 0);
        CP_COMMIT();
    }

    float pv[64];
#pragma unroll
    for (int k = 0; k < 64; k++) pv[k] = 0.0f;
    float lacc0 = 0.0f, lacc1 = 0.0f;
    u32 aq[4];

    // ---- prologue: t = 0 (S only) ----
    {
        stage_K(cx, cx.sb + SM_K1, Ktb, BJ);
        CP_COMMIT();
        CP_WAIT(1);
        __syncthreads();
        const int rowA = cx.mr + ((cx.mat & 1) << 3) + cx.rr;
        ldsm4(aq[0], aq[1], aq[2], aq[3], cx.sb + SM_Q + kswz(rowA, cx.mat >> 1));
        s_phase(cx, smem, cx.sb + SM_K0, SM_P0, aq, lacc0, lacc1);
    }

    // ---- steady state: t = 1..NT-1 ----
#pragma unroll 1
    for (int t = 1; t < NT; t++) {
        const u32 kcur  = (t & 1) ? cx.sb + SM_K1 : cx.sb + SM_K0;
        const u32 knext = (t & 1) ? cx.sb + SM_K0 : cx.sb + SM_K1;
        const u32 pofs  = (t & 1) ? SM_P1 : SM_P0;
        const u32 pprev = (t & 1) ? cx.sb + SM_P0 : cx.sb + SM_P1;

        if (t < NT - 1) { stage_K(cx, knext, Ktb, (t + 1) * BJ); CP_COMMIT(); CP_WAIT(1); }
        else            { CP_WAIT(0); }
        __syncthreads();

        s_phase(cx, smem, kcur, pofs, aq, lacc0, lacc1);
        pv_phase(cx, pprev, cx.sb + SM_V, pv);
        __syncthreads();

        stage_V(cx, cx.sb + SM_V, Vb, t * BJ);
        CP_COMMIT();
    }

    // ---- epilogue tile: PV(NT-1) ----
    CP_WAIT(0);
    __syncthreads();
    pv_phase(cx, cx.sb + SM_P1, cx.sb + SM_V, pv);

    // ---- softmax denominator ----
    lacc0 += __shfl_xor_sync(0xFFFFFFFFu, lacc0, 1);
    lacc0 += __shfl_xor_sync(0xFFFFFFFFu, lacc0, 2);
    lacc1 += __shfl_xor_sync(0xFFFFFFFFu, lacc1, 1);
    lacc1 += __shfl_xor_sync(0xFFFFFFFFu, lacc1, 2);
    __syncthreads();
    if ((cx.lane & 3) == 0) {
        const int q0 = cx.mr + (cx.lane >> 2);
        *(float*)(smem + SM_L + (q0 * 2 + jh) * 4)       = lacc0;
        *(float*)(smem + SM_L + ((q0 + 8) * 2 + jh) * 4) = lacc1;
    }
    __syncthreads();
    if (cx.tid < 64) {
        float s = *(float*)(smem + SM_L + (cx.tid * 2) * 4)
                + *(float*)(smem + SM_L + (cx.tid * 2 + 1) * 4);
        *(float*)(smem + SM_INV + cx.tid * 4) = 1.0f / s;
    }
    __syncthreads();

    // ---- epilogue: coalesced via SMEM transpose (f32 [256c][17] at smem base) ----
    const float g = gamma[0];
    const float* xb = x   + ((size_t)b * C_) * N_ + i0;
    float*       ob = out + ((size_t)b * C_) * N_ + i0;

#pragma unroll 1
    for (int qblk = 0; qblk < 4; qblk++) {
        const int mt = qblk;
#pragma unroll
        for (int np = 0; np < 2; np++)
#pragma unroll
            for (int h = 0; h < 2; h++)
#pragma unroll
                for (int e2 = 0; e2 < 2; e2++) {
                    int qloc = (cx.lane >> 2) + e2 * 8;
                    int c = cx.cb + np * 16 + h * 8 + (cx.lane & 3) * 2;
                    float il = *(const float*)(smem + SM_INV + (qblk * 16 + qloc) * 4);
                    float v0 = pv[(mt * 4 + np * 2 + h) * 4 + e2 * 2 + 0];
                    float v1 = pv[(mt * 4 + np * 2 + h) * 4 + e2 * 2 + 1];
                    *(float*)(smem + (c * 17 + qloc) * 4)       = g * v0 * il;
                    *(float*)(smem + ((c + 1) * 17 + qloc) * 4) = g * v1 * il;
                }
        __syncthreads();
#pragma unroll
        for (int i = 0; i < 16; i++) {
            int e = i * 256 + cx.tid;
            int c = e >> 4, q = e & 15;
            int qg = qblk * 16 + q;
            ob[(size_t)c * N_ + qg] = *(const float*)(smem + (c * 17 + q) * 4)
                                    + xb[(size_t)c * N_ + qg];
        }
        __syncthreads();
    }
}

// ------------------------- launch -------------------------
extern "C" void kernel_launch(void* const* d_in, const int* in_sizes, int n_in,
                              void* d_out, int out_size)
{
    (void)in_sizes; (void)n_in; (void)out_size;
    const float* x     = (const float*)d_in[0];
    const float* Wq    = (const float*)d_in[1];
    const float* bq    = (const float*)d_in[2];
    const float* Wk    = (const float*)d_in[3];
    const float* bk    = (const float*)d_in[4];
    const float* Wv    = (const float*)d_in[5];
    const float* bv    = (const float*)d_in[6];
    const float* gamma = (const float*)d_in[7];
    float* out = (float*)d_out;

    cudaFuncSetAttribute(proj_kernel, cudaFuncAttributeMaxDynamicSharedMemorySize, PSMEM_SZ);
    cudaFuncSetAttribute(attn_kernel, cudaFuncAttributeMaxDynamicSharedMemorySize, SMEM_SZ);

    dim3 blk(256);
    proj_kernel<<<dim3(N_ / 256, 10, B_), blk, PSMEM_SZ>>>(x, Wq, bq, Wk, bk, Wv, bv);
    attn_kernel<<<dim3(N_ / BI, B_), blk, SMEM_SZ>>>(x, gamma, out);
}

// round 14
// speedup vs baseline: 1.0992x; 1.0992x over previous
#include <cuda_runtime.h>
#include <cuda_bf16.h>
#include <cstdint>

typedef unsigned long long u64;
typedef uint32_t u32;
typedef unsigned short u16;
typedef unsigned char u8;

#define DEV_INLINE __device__ __forceinline__

// ------------------------- constants -------------------------
static constexpr int B_ = 4;
static constexpr int C_ = 256;
static constexpr int D_ = 32;     // C/8
static constexpr int N_ = 4096;   // 64*64
static constexpr int BI = 64;     // queries per CTA
static constexpr int BJ = 256;    // keys per j-tile
static constexpr int NT = N_ / BJ; // 16 tiles

// softmax scale folded into Q/K quantization:
// Q' = Q * log2(e)/4, K' = K/4  ->  S_mma = S * log2(e)/16 = ex2 argument
#define Q_SCL 0.36067376022224085f
#define K_SCL 0.25f

// fp8 scratch (static device globals — allocation-free per harness rules)
__device__ __align__(16) u8 g_Qt8[B_ * N_ * 32];   // [b][n][32d] e4m3, 32B rows
__device__ __align__(16) u8 g_Kt8[B_ * N_ * 32];   // [b][n][32d]
__device__ __align__(16) u8 g_V8 [B_ * C_ * N_];   // [b][c][n]  e4m3

// ------------------------- helpers -------------------------
DEV_INLINE u32 smem_u32(const void* p) {
    u32 a; asm("{ .reg .u64 t; cvta.to.shared.u64 t, %1; cvt.u32.u64 %0, t; }" : "=r"(a) : "l"(p));
    return a;
}
DEV_INLINE u64 pk2(float a, float b) { u64 r; asm("mov.b64 %0, {%1,%2};" : "=l"(r) : "f"(a), "f"(b)); return r; }
DEV_INLINE void upk2(u64 v, float& a, float& b) { asm("mov.b64 {%0,%1}, %2;" : "=f"(a), "=f"(b) : "l"(v)); }
DEV_INLINE void fma2(u64& d, u64 a, u64 b) { asm("fma.rn.f32x2 %0, %1, %2, %0;" : "+l"(d) : "l"(a), "l"(b)); }

DEV_INLINE void ldsm4(u32& r0, u32& r1, u32& r2, u32& r3, u32 addr) {
    asm volatile("ldmatrix.sync.aligned.m8n8.x4.shared.b16 {%0,%1,%2,%3}, [%4];"
                 : "=r"(r0), "=r"(r1), "=r"(r2), "=r"(r3) : "r"(addr));
}
// fp8 e4m3 mma: D(f32) = A(16x32 e4m3) * B(8x32 e4m3)^T + D
DEV_INLINE void mmafp8(float* c, const u32* a, u32 b0, u32 b1) {
    asm volatile(
        "mma.sync.aligned.m16n8k32.row.col.f32.e4m3.e4m3.f32 "
        "{%0,%1,%2,%3}, {%4,%5,%6,%7}, {%8,%9}, {%0,%1,%2,%3};"
        : "+f"(c[0]), "+f"(c[1]), "+f"(c[2]), "+f"(c[3])
        : "r"(a[0]), "r"(a[1]), "r"(a[2]), "r"(a[3]), "r"(b0), "r"(b1));
}
DEV_INLINE u16 e4m3x2(float hi, float lo) {
    u16 r; asm("cvt.rn.satfinite.e4m3x2.f32 %0, %1, %2;" : "=h"(r) : "f"(hi), "f"(lo)); return r;
}
DEV_INLINE float ex2f(float s) {
    float e; asm("ex2.approx.ftz.f32 %0, %1;" : "=f"(e) : "f"(s)); return e;
}
DEV_INLINE void cpa16(u32 dst, const void* src) {
    asm volatile("cp.async.cg.shared.global [%0], [%1], 16;" :: "r"(dst), "l"(src));
}
#define CP_COMMIT() asm volatile("cp.async.commit_group;" ::: "memory")
#define CP_WAIT(n)  asm volatile("cp.async.wait_group %0;" :: "n"(n) : "memory")

// Q/K tiles: 32B rows (32 e4m3 of d); 16B chunk ^= row>>2
DEV_INLINE u32 kswz(int row, int c) { return (u32)(row * 32 + (((c ^ (row >> 2)) & 1) << 4)); }
// V/P tiles: 256B rows; 16B chunk ^= row&7
DEV_INLINE u32 vswz(int row, int ch) { return (u32)(row * 256 + ((ch ^ (row & 7)) << 4)); }

// attn SMEM layout (dynamic, bytes)
static constexpr int SM_P1  = 0;
static constexpr int SM_Q   = 0;
static constexpr int SM_P0  = 16384;
static constexpr int SM_K0  = 32768;
static constexpr int SM_K1  = 40960;
static constexpr int SM_V   = 49152;
static constexpr int SM_L   = 114688;
static constexpr int SM_INV = 115200;
static constexpr int SMEM_SZ = 115456;

// proj SMEM: Ws f32[256][34] + 2 x-chunk buffers [16ch][512n] f32
static constexpr int PSM_WS  = 0;
static constexpr int PSM_X0  = 34816;
static constexpr int PSM_X1  = 67584;
static constexpr int PSMEM_SZ = 100352;

// ------------------------- unified projection kernel -------------------------
// grid (N/512, 10, B): y<8 -> V rows y*32 (e4m3 [c][n]); y==8 -> Q'; y==9 -> K'
// (both transposed [n][32] e4m3; Q' and K' carry the folded softmax scales).
__global__ __launch_bounds__(256) void proj_kernel(
    const float* __restrict__ x,
    const float* __restrict__ Wq, const float* __restrict__ bq,
    const float* __restrict__ Wk, const float* __restrict__ bk,
    const float* __restrict__ Wv, const float* __restrict__ bv)
{
    extern __shared__ __align__(16) char psm[];
    const u32 psb = smem_u32(psm);
    float* Ws = (float*)(psm + PSM_WS);
    const u32 xbuf[2] = { psb + PSM_X0, psb + PSM_X1 };

    const int tid = threadIdx.x;
    const int nbase = blockIdx.x * 512;
    const int n0 = nbase + tid * 2;
    const int y  = blockIdx.y;
    const int b  = blockIdx.z;

    const float* W; const float* bias; int r0; int mode;
    if (y < 8)       { W = Wv; bias = bv; r0 = y * 32; mode = 0; }
    else if (y == 8) { W = Wq; bias = bq; r0 = 0;      mode = 1; }
    else             { W = Wk; bias = bk; r0 = 0;      mode = 2; }

    for (int idx = tid; idx < 32 * 256; idx += 256) {
        int r = idx >> 8, c = idx & 255;
        Ws[c * 34 + r] = W[(r0 + r) * 256 + c];
    }

    const char* xb = (const char*)(x + ((size_t)b * C_) * N_ + nbase);
    {
#pragma unroll
        for (int it = 0; it < 8; it++) {
            int idx = tid + it * 256;
            int row = idx >> 7, off = (idx & 127) << 4;
            cpa16(xbuf[0] + row * 2048 + off, xb + (size_t)row * (N_ * 4) + off);
        }
        CP_COMMIT();
    }

    u64 accA[16], accB[16];
#pragma unroll
    for (int k = 0; k < 16; k++) { accA[k] = 0ull; accB[k] = 0ull; }

#pragma unroll 1
    for (int ch = 0; ch < 16; ch++) {
        if (ch < 15) {
            const int c1 = (ch + 1) * 16;
#pragma unroll
            for (int it = 0; it < 8; it++) {
                int idx = tid + it * 256;
                int row = idx >> 7, off = (idx & 127) << 4;
                cpa16(xbuf[(ch + 1) & 1] + row * 2048 + off,
                      xb + (size_t)(c1 + row) * (N_ * 4) + off);
            }
            CP_COMMIT();
            CP_WAIT(1);
        } else {
            CP_WAIT(0);
        }
        __syncthreads();

        const char* xs = (const char*)psm + (xbuf[ch & 1] - psb);
#pragma unroll
        for (int cc = 0; cc < 16; cc++) {
            const int c = ch * 16 + cc;
            float2 v = *(const float2*)(xs + cc * 2048 + tid * 8);
            u64 a2 = pk2(v.x, v.x), b2 = pk2(v.y, v.y);
            const u64* wrow = (const u64*)&Ws[c * 34];
#pragma unroll
            for (int k = 0; k < 16; k++) { fma2(accA[k], wrow[k], a2); fma2(accB[k], wrow[k], b2); }
        }
        __syncthreads();
    }

    if (mode == 0) {
        u8* ob = g_V8 + ((size_t)b * C_ + r0) * N_ + n0;
#pragma unroll
        for (int k = 0; k < 16; k++) {
            float alo, ahi, blo, bhi;
            upk2(accA[k], alo, ahi); upk2(accB[k], blo, bhi);
            float b0 = bias[r0 + 2 * k], b1 = bias[r0 + 2 * k + 1];
            *(u16*)(ob + (size_t)(2 * k) * N_)     = e4m3x2(blo + b0, alo + b0);
            *(u16*)(ob + (size_t)(2 * k + 1) * N_) = e4m3x2(bhi + b1, ahi + b1);
        }
    } else {
        u8* base = (mode == 1) ? g_Qt8 : g_Kt8;
        const float scl = (mode == 1) ? Q_SCL : K_SCL;
#pragma unroll
        for (int half = 0; half < 2; half++) {
            const u64* acc = half ? accB : accA;
            u32 h[8];
#pragma unroll
            for (int j = 0; j < 8; j++) {
                float l0, h0, l1, h1;
                upk2(acc[2 * j], l0, h0); upk2(acc[2 * j + 1], l1, h1);
                u16 wa = e4m3x2((h0 + bias[4 * j + 1]) * scl, (l0 + bias[4 * j]) * scl);
                u16 wb = e4m3x2((h1 + bias[4 * j + 3]) * scl, (l1 + bias[4 * j + 2]) * scl);
                h[j] = (u32)wa | ((u32)wb << 16);
            }
            uint4* op = (uint4*)(base + ((size_t)b * N_ + n0 + half) * 32);
            op[0] = make_uint4(h[0], h[1], h[2], h[3]);
            op[1] = make_uint4(h[4], h[5], h[6], h[7]);
        }
    }
}

// ------------------------- attention device helpers -------------------------
struct AttnCtx {
    u32 sb; int tid, lane, warp, rr, mat, mr, jb, cb;
};

// S = Q'.K'^T (warp: 16q x 128j) -> mma output IS the ex2 argument; e4m3 P write
DEV_INLINE void s_phase(const AttnCtx& cx, char* smem, u32 kbuf, u32 pofs,
                        const u32 aq[4], float& lacc0, float& lacc1)
{
    const int q0 = cx.mr + (cx.lane >> 2);
    const int jl = 2 * (cx.lane & 3);
    const u32 prow0 = pofs + q0 * 256 + ((q0 & 7) << 4);
    const u32 prow8 = prow0 + 8 * 256;
#pragma unroll
    for (int nbp = 0; nbp < 8; nbp++) {
        const int jcol = cx.jb + nbp * 16;
        const int rowB = jcol + ((cx.mat >> 1) << 3) + cx.rr;
        u32 b0, b1, b2, b3;
        ldsm4(b0, b1, b2, b3, kbuf + kswz(rowB, cx.mat & 1));
        float s[8] = {0.f,0.f,0.f,0.f,0.f,0.f,0.f,0.f};
        mmafp8(&s[0], aq, b0, b1);
        mmafp8(&s[4], aq, b2, b3);
        float e0 = ex2f(s[0]), e1 = ex2f(s[1]);
        float e2 = ex2f(s[2]), e3 = ex2f(s[3]);
        float e4 = ex2f(s[4]), e5 = ex2f(s[5]);
        float e6 = ex2f(s[6]), e7 = ex2f(s[7]);
        lacc0 += (e0 + e1) + (e4 + e5);
        lacc1 += (e2 + e3) + (e6 + e7);
        const u32 csw = (u32)(((jcol >> 4) ^ (q0 & 7)) << 4) - (u32)((q0 & 7) << 4);
        *(u16*)(smem + prow0 + csw + jl)     = e4m3x2(e1, e0);
        *(u16*)(smem + prow0 + csw + jl + 8) = e4m3x2(e5, e4);
        *(u16*)(smem + prow8 + csw + jl)     = e4m3x2(e3, e2);
        *(u16*)(smem + prow8 + csw + jl + 8) = e4m3x2(e7, e6);
    }
}

// O += P.V^T (warp: 64q x 32c, K = 256 j)
DEV_INLINE void pv_phase(const AttnCtx& cx, u32 pbuf, u32 vbuf, float pv[64])
{
#pragma unroll
    for (int kk = 0; kk < 8; kk++) {
        u32 ap[4][4];
#pragma unroll
        for (int mt = 0; mt < 4; mt++) {
            const int rowA = mt * 16 + ((cx.mat & 1) << 3) + cx.rr;
            ldsm4(ap[mt][0], ap[mt][1], ap[mt][2], ap[mt][3],
                  pbuf + vswz(rowA, kk * 2 + (cx.mat >> 1)));
        }
#pragma unroll
        for (int np = 0; np < 2; np++) {
            const int rowV = cx.cb + np * 16 + ((cx.mat >> 1) << 3) + cx.rr;
            u32 b0, b1, b2, b3;
            ldsm4(b0, b1, b2, b3, vbuf + vswz(rowV, kk * 2 + (cx.mat & 1)));
#pragma unroll
            for (int mt = 0; mt < 4; mt++) {
                mmafp8(&pv[(mt * 4 + np * 2) * 4],     ap[mt], b0, b1);
                mmafp8(&pv[(mt * 4 + np * 2 + 1) * 4], ap[mt], b2, b3);
            }
        }
    }
}

DEV_INLINE void stage_K(const AttnCtx& cx, u32 kbuf, const u8* Ktb, int j0) {
#pragma unroll
    for (int it = 0; it < 2; it++) {
        int idx = cx.tid + it * 256;
        int row = idx >> 1, c = idx & 1;
        cpa16(kbuf + kswz(row, c), Ktb + (size_t)(j0 + row) * 32 + c * 16);
    }
}
DEV_INLINE void stage_V(const AttnCtx& cx, u32 vbuf, const u8* Vb, int j0) {
#pragma unroll
    for (int it = 0; it < 16; it++) {
        int idx = cx.tid + it * 256;
        int row = idx >> 4, ch = idx & 15;
        cpa16(vbuf + vswz(row, ch), Vb + (size_t)row * N_ + j0 + ch * 16);
    }
}

// ------------------------- attention kernel -------------------------
// grid (N/64, B), 256 threads (8 warps), 2 CTAs/SM, fp8 operands.
// Skewed pipeline: iter t computes S(t) then PV(t-1). NT=16 tiles of 256 j.
__global__ __launch_bounds__(256, 2) void attn_kernel(
    const float* __restrict__ x, const float* __restrict__ gamma,
    float* __restrict__ out)
{
    extern __shared__ __align__(1024) char smem[];
    AttnCtx cx;
    cx.sb = smem_u32(smem);
    cx.tid = threadIdx.x;
    cx.lane = cx.tid & 31;
    cx.warp = cx.tid >> 5;
    cx.rr = cx.lane & 7;
    cx.mat = cx.lane >> 3;
    cx.mr = (cx.warp >> 1) * 16;
    cx.jb = (cx.warp & 1) * 128;
    cx.cb = cx.warp * 32;
    const int jh = cx.warp & 1;
    const int i0 = blockIdx.x * BI;
    const int b  = blockIdx.y;

    const u8* Qtb = g_Qt8 + (size_t)b * N_ * 32;
    const u8* Ktb = g_Kt8 + (size_t)b * N_ * 32;
    const u8* Vb  = g_V8  + (size_t)b * C_ * N_;

    // ---- pre-loop staging: {Q, K0} group, {V0} group ----
    {
        if (cx.tid < 128) {
            int row = cx.tid >> 1, c = cx.tid & 1;
            cpa16(cx.sb + SM_Q + kswz(row, c), Qtb + (size_t)(i0 + row) * 32 + c * 16);
        }
        stage_K(cx, cx.sb + SM_K0, Ktb, 0);
        CP_COMMIT();
        stage_V(cx, cx.sb + SM_V, Vb, 0);
        CP_COMMIT();
    }

    float pv[64];
#pragma unroll
    for (int k = 0; k < 64; k++) pv[k] = 0.0f;
    float lacc0 = 0.0f, lacc1 = 0.0f;
    u32 aq[4];

    // ---- prologue: t = 0 (S only) ----
    {
        stage_K(cx, cx.sb + SM_K1, Ktb, BJ);
        CP_COMMIT();
        CP_WAIT(1);
        __syncthreads();
        const int rowA = cx.mr + ((cx.mat & 1) << 3) + cx.rr;
        ldsm4(aq[0], aq[1], aq[2], aq[3], cx.sb + SM_Q + kswz(rowA, cx.mat >> 1));
        s_phase(cx, smem, cx.sb + SM_K0, SM_P0, aq, lacc0, lacc1);
    }

    // ---- steady state: t = 1..NT-1 ----
#pragma unroll 1
    for (int t = 1; t < NT; t++) {
        const u32 kcur  = (t & 1) ? cx.sb + SM_K1 : cx.sb + SM_K0;
        const u32 knext = (t & 1) ? cx.sb + SM_K0 : cx.sb + SM_K1;
        const u32 pofs  = (t & 1) ? SM_P1 : SM_P0;
        const u32 pprev = (t & 1) ? cx.sb + SM_P0 : cx.sb + SM_P1;

        if (t < NT - 1) { stage_K(cx, knext, Ktb, (t + 1) * BJ); CP_COMMIT(); CP_WAIT(1); }
        else            { CP_WAIT(0); }
        __syncthreads();

        s_phase(cx, smem, kcur, pofs, aq, lacc0, lacc1);
        pv_phase(cx, pprev, cx.sb + SM_V, pv);
        __syncthreads();

        stage_V(cx, cx.sb + SM_V, Vb, t * BJ);
        CP_COMMIT();
    }

    // ---- epilogue tile: PV(NT-1) ----
    CP_WAIT(0);
    __syncthreads();
    pv_phase(cx, cx.sb + SM_P1, cx.sb + SM_V, pv);

    // ---- softmax denominator ----
    lacc0 += __shfl_xor_sync(0xFFFFFFFFu, lacc0, 1);
    lacc0 += __shfl_xor_sync(0xFFFFFFFFu, lacc0, 2);
    lacc1 += __shfl_xor_sync(0xFFFFFFFFu, lacc1, 1);
    lacc1 += __shfl_xor_sync(0xFFFFFFFFu, lacc1, 2);
    __syncthreads();
    if ((cx.lane & 3) == 0) {
        const int q0 = cx.mr + (cx.lane >> 2);
        *(float*)(smem + SM_L + (q0 * 2 + jh) * 4)       = lacc0;
        *(float*)(smem + SM_L + ((q0 + 8) * 2 + jh) * 4) = lacc1;
    }
    __syncthreads();
    if (cx.tid < 64) {
        float s = *(float*)(smem + SM_L + (cx.tid * 2) * 4)
                + *(float*)(smem + SM_L + (cx.tid * 2 + 1) * 4);
        *(float*)(smem + SM_INV + cx.tid * 4) = 1.0f / s;
    }
    __syncthreads();

    // ---- epilogue: coalesced via SMEM transpose (f32 [256c][17] at smem base) ----
    const float g = gamma[0];
    const float* xb = x   + ((size_t)b * C_) * N_ + i0;
    float*       ob = out + ((size_t)b * C_) * N_ + i0;

#pragma unroll 1
    for (int qblk = 0; qblk < 4; qblk++) {
        const int mt = qblk;
#pragma unroll
        for (int np = 0; np < 2; np++)
#pragma unroll
            for (int h = 0; h < 2; h++)
#pragma unroll
                for (int e2 = 0; e2 < 2; e2++) {
                    int qloc = (cx.lane >> 2) + e2 * 8;
                    int c = cx.cb + np * 16 + h * 8 + (cx.lane & 3) * 2;
                    float il = *(const float*)(smem + SM_INV + (qblk * 16 + qloc) * 4);
                    float v0 = pv[(mt * 4 + np * 2 + h) * 4 + e2 * 2 + 0];
                    float v1 = pv[(mt * 4 + np * 2 + h) * 4 + e2 * 2 + 1];
                    *(float*)(smem + (c * 17 + qloc) * 4)       = g * v0 * il;
                    *(float*)(smem + ((c + 1) * 17 + qloc) * 4) = g * v1 * il;
                }
        __syncthreads();
#pragma unroll
        for (int i = 0; i < 16; i++) {
            int e = i * 256 + cx.tid;
            int c = e >> 4, q = e & 15;
            int qg = qblk * 16 + q;
            ob[(size_t)c * N_ + qg] = *(const float*)(smem + (c * 17 + q) * 4)
                                    + xb[(size_t)c * N_ + qg];
        }
        __syncthreads();
    }
}

// ------------------------- launch -------------------------
extern "C" void kernel_launch(void* const* d_in, const int* in_sizes, int n_in,
                              void* d_out, int out_size)
{
    (void)in_sizes; (void)n_in; (void)out_size;
    const float* x     = (const float*)d_in[0];
    const float* Wq    = (const float*)d_in[1];
    const float* bq    = (const float*)d_in[2];
    const float* Wk    = (const float*)d_in[3];
    const float* bk    = (const float*)d_in[4];
    const float* Wv    = (const float*)d_in[5];
    const float* bv    = (const float*)d_in[6];
    const float* gamma = (const float*)d_in[7];
    float* out = (float*)d_out;

    cudaFuncSetAttribute(proj_kernel, cudaFuncAttributeMaxDynamicSharedMemorySize, PSMEM_SZ);
    cudaFuncSetAttribute(attn_kernel, cudaFuncAttributeMaxDynamicSharedMemorySize, SMEM_SZ);

    dim3 blk(256);
    proj_kernel<<<dim3(N_ / 512, 10, B_), blk, PSMEM_SZ>>>(x, Wq, bq, Wk, bk, Wv, bv);
    attn_kernel<<<dim3(N_ / BI, B_), blk, SMEM_SZ>>>(x, gamma, out);
}

// round 16
// speedup vs baseline: 1.4127x; 1.2852x over previous
#include <cuda_runtime.h>
#include <cuda_bf16.h>
#include <cstdint>

typedef unsigned long long u64;
typedef uint32_t u32;
typedef unsigned short u16;
typedef unsigned char u8;

#define DEV_INLINE __device__ __forceinline__

// ------------------------- constants -------------------------
static constexpr int B_ = 4;
static constexpr int C_ = 256;
static constexpr int D_ = 32;     // C/8
static constexpr int N_ = 4096;   // 64*64
static constexpr int BI = 64;     // queries per CTA (attn)
static constexpr int BJ = 256;    // keys per j-tile (attn)
static constexpr int NT = N_ / BJ;

// softmax scale folded into Q/K weights: Q' = Q*log2(e)/4, K' = K/4
#define Q_SCL 0.36067376022224085f
#define K_SCL 0.25f

// fp8 scratch (static device globals — allocation-free per harness rules)
__device__ __align__(16) u8 g_Qt8[B_ * N_ * 32];   // [b][n][32d] e4m3
__device__ __align__(16) u8 g_Kt8[B_ * N_ * 32];   // [b][n][32d]
__device__ __align__(16) u8 g_V8 [B_ * C_ * N_];   // [b][c][n]  e4m3
// pre-swizzled bf16 weights: 5 blocks of 64 rows x 256 k (rows: Q0-31,K0-31,V0-255)
__device__ __align__(16) u8 g_Wb[5 * 64 * 512];
__device__ float g_bias[320];

// ------------------------- helpers -------------------------
DEV_INLINE u32 smem_u32(const void* p) {
    u32 a; asm("{ .reg .u64 t; cvta.to.shared.u64 t, %1; cvt.u32.u64 %0, t; }" : "=r"(a) : "l"(p));
    return a;
}
DEV_INLINE void ldsm4(u32& r0, u32& r1, u32& r2, u32& r3, u32 addr) {
    asm volatile("ldmatrix.sync.aligned.m8n8.x4.shared.b16 {%0,%1,%2,%3}, [%4];"
                 : "=r"(r0), "=r"(r1), "=r"(r2), "=r"(r3) : "r"(addr));
}
DEV_INLINE void ldsm4t(u32& r0, u32& r1, u32& r2, u32& r3, u32 addr) {
    asm volatile("ldmatrix.sync.aligned.m8n8.x4.trans.shared.b16 {%0,%1,%2,%3}, [%4];"
                 : "=r"(r0), "=r"(r1), "=r"(r2), "=r"(r3) : "r"(addr));
}
DEV_INLINE void mmabf(float* c, const u32* a, u32 b0, u32 b1) {
    asm volatile(
        "mma.sync.aligned.m16n8k16.row.col.f32.bf16.bf16.f32 "
        "{%0,%1,%2,%3}, {%4,%5,%6,%7}, {%8,%9}, {%0,%1,%2,%3};"
        : "+f"(c[0]), "+f"(c[1]), "+f"(c[2]), "+f"(c[3])
        : "r"(a[0]), "r"(a[1]), "r"(a[2]), "r"(a[3]), "r"(b0), "r"(b1));
}
DEV_INLINE void mmafp8(float* c, const u32* a, u32 b0, u32 b1) {
    asm volatile(
        "mma.sync.aligned.m16n8k32.row.col.f32.e4m3.e4m3.f32 "
        "{%0,%1,%2,%3}, {%4,%5,%6,%7}, {%8,%9}, {%0,%1,%2,%3};"
        : "+f"(c[0]), "+f"(c[1]), "+f"(c[2]), "+f"(c[3])
        : "r"(a[0]), "r"(a[1]), "r"(a[2]), "r"(a[3]), "r"(b0), "r"(b1));
}
DEV_INLINE u16 e4m3x2(float hi, float lo) {
    u16 r; asm("cvt.rn.satfinite.e4m3x2.f32 %0, %1, %2;" : "=h"(r) : "f"(hi), "f"(lo)); return r;
}
DEV_INLINE u8 e4m3_1(float v) { return (u8)e4m3x2(0.0f, v); }
DEV_INLINE u32 bf16x2(float hi, float lo) {
    u32 r; asm("cvt.rn.bf16x2.f32 %0, %1, %2;" : "=r"(r) : "f"(hi), "f"(lo)); return r;
}
DEV_INLINE float ex2f(float s) {
    float e; asm("ex2.approx.ftz.f32 %0, %1;" : "=f"(e) : "f"(s)); return e;
}
DEV_INLINE void cpa16(u32 dst, const void* src) {
    asm volatile("cp.async.cg.shared.global [%0], [%1], 16;" :: "r"(dst), "l"(src));
}
#define CP_COMMIT() asm volatile("cp.async.commit_group;" ::: "memory")
#define CP_WAIT(n)  asm volatile("cp.async.wait_group %0;" :: "n"(n) : "memory")

// attn Q/K tiles: 32B rows; 16B chunk ^= row>>2
DEV_INLINE u32 kswz(int row, int c) { return (u32)(row * 32 + (((c ^ (row >> 2)) & 1) << 4)); }
// attn V/P tiles: 256B rows; 16B chunk ^= row&7
DEV_INLINE u32 vswz(int row, int ch) { return (u32)(row * 256 + ((ch ^ (row & 7)) << 4)); }

// attn SMEM layout
static constexpr int SM_P1  = 0;
static constexpr int SM_Q   = 0;
static constexpr int SM_P0  = 16384;
static constexpr int SM_K0  = 32768;
static constexpr int SM_K1  = 40960;
static constexpr int SM_V   = 49152;
static constexpr int SM_L   = 114688;
static constexpr int SM_INV = 115200;
static constexpr int SMEM_SZ = 115456;

// proj2 SMEM: xs bf16 [256k][64n] (128B rows) + 2 W tile buffers (64r x 512B)
static constexpr int P2_XS  = 0;        // 32 KB
static constexpr int P2_W0  = 32768;    // 32 KB
static constexpr int P2_W1  = 65536;    // 32 KB
static constexpr int P2SMEM = 98304;

// ------------------------- weight prep kernel -------------------------
// grid (320), 256 thr: row -> bf16, scale folded, swizzled into g_Wb tile layout.
__global__ void prep_kernel(
    const float* __restrict__ Wq, const float* __restrict__ bq,
    const float* __restrict__ Wk, const float* __restrict__ bk,
    const float* __restrict__ Wv, const float* __restrict__ bv)
{
    const int row = blockIdx.x;        // 0..319
    const int c = threadIdx.x;         // 0..255
    const float* src; float scl, bias;
    if (row < 32)      { src = Wq + row * 256;        scl = Q_SCL; bias = bq[row]; }
    else if (row < 64) { src = Wk + (row - 32) * 256; scl = K_SCL; bias = bk[row - 32]; }
    else               { src = Wv + (row - 64) * 256; scl = 1.0f;  bias = bv[row - 64]; }
    const int blk = row >> 6, r = row & 63;
    __nv_bfloat16 h = __float2bfloat16_rn(src[c] * scl);
    *(__nv_bfloat16*)(g_Wb + blk * 32768 + r * 512 + (((c >> 3) ^ (r & 7)) << 4) + (c & 7) * 2) = h;
    if (c == 0) g_bias[row] = bias * scl;
}

// ------------------------- projection GEMM kernel (bf16 mma) -------------------------
// grid (N/64, B), 256 thr, 2 CTAs/SM. Per CTA: x-tile [256c x 64n] staged once;
// 5 W blocks of 64 rows streamed via cp.async; out = W@x -> e4m3 Q'/K'/V.
__global__ __launch_bounds__(256, 2) void proj2_kernel(const float* __restrict__ x)
{
    extern __shared__ __align__(1024) char sm2[];
    const u32 sb = smem_u32(sm2);
    const u32 WT[2] = { sb + P2_W0, sb + P2_W1 };
    const int tid  = threadIdx.x;
    const int lane = tid & 31;
    const int warp = tid >> 5;
    const int rr  = lane & 7;
    const int mat = lane >> 3;
    const int mr  = (warp >> 1) * 16;      // row base within 64-row block
    const int nwb = (warp & 1) * 32;       // n base within 64-n tile
    const int n0 = blockIdx.x * 64;
    const int b  = blockIdx.y;

    // stage W block 0
#pragma unroll
    for (int it = 0; it < 8; it++) {
        int idx = tid + it * 256;
        cpa16(WT[0] + idx * 16, g_Wb + idx * 16);
    }
    CP_COMMIT();

    // x prologue: f32 -> bf16 into xs [c][n], swizzled 16B chunks (^= c&7)
    const float* xb = x + ((size_t)b * C_) * N_ + n0;
#pragma unroll 4
    for (int it = 0; it < 32; it++) {
        int idx = tid + it * 256;
        int c = idx >> 5, np = (idx & 31) * 2;
        float2 v = *(const float2*)&xb[(size_t)c * N_ + np];
        u32 p = bf16x2(v.y, v.x);
        *(u32*)(sm2 + P2_XS + c * 128 + ((((np >> 3) ^ (c & 7)) << 4)) + (np & 7) * 2) = p;
    }

#pragma unroll 1
    for (int blk = 0; blk < 5; blk++) {
        const u32 wcur = WT[blk & 1];
        if (blk < 4) {
            const u32 wnext = WT[(blk + 1) & 1];
#pragma unroll
            for (int it = 0; it < 8; it++) {
                int idx = tid + it * 256;
                cpa16(wnext + idx * 16, g_Wb + (blk + 1) * 32768 + idx * 16);
            }
            CP_COMMIT();
            CP_WAIT(1);
        } else {
            CP_WAIT(0);
        }
        __syncthreads();

        float acc[16];
#pragma unroll
        for (int k = 0; k < 16; k++) acc[k] = 0.0f;

#pragma unroll 4
        for (int ks = 0; ks < 16; ks++) {
            // A = W rows [mr..mr+15], k = ks*16..+15 (non-trans ldsm)
            u32 a[4];
            {
                const int rowA = mr + (mat & 1) * 8 + rr;
                const int ch = ks * 2 + (mat >> 1);
                ldsm4(a[0], a[1], a[2], a[3],
                      wcur + rowA * 512 + (((ch ^ (rowA & 7)) << 4)));
            }
            // B = x^T via ldmatrix.trans on xs[k][n]
#pragma unroll
            for (int half = 0; half < 2; half++) {
                const int krow = ks * 16 + (mat & 1) * 8 + rr;
                const int ncol = nwb + half * 16 + (mat >> 1) * 8;
                u32 b0, b1, b2, b3;
                ldsm4t(b0, b1, b2, b3,
                       sb + P2_XS + krow * 128 + ((((ncol >> 3) ^ (krow & 7)) << 4)));
                mmabf(&acc[(half * 2) * 4],     a, b0, b1);
                mmabf(&acc[(half * 2 + 1) * 4], a, b2, b3);
            }
        }

        // epilogue
        const int rl = mr + (lane >> 2);
        const float bias0 = g_bias[blk * 64 + rl];
        const float bias8 = g_bias[blk * 64 + rl + 8];
        if (blk == 0) {
            // Q rows 0-31 / K rows 0-31, transposed byte layout [n][32]
            u8* dst; int r;
            if (rl < 32) { dst = g_Qt8 + ((size_t)b * N_ + n0) * 32; r = rl; }
            else         { dst = g_Kt8 + ((size_t)b * N_ + n0) * 32; r = rl - 32; }
#pragma unroll
            for (int nb = 0; nb < 4; nb++) {
                int n = nwb + nb * 8 + (lane & 3) * 2;
                dst[(size_t)n * 32 + r]           = e4m3_1(acc[nb * 4 + 0] + bias0);
                dst[(size_t)(n + 1) * 32 + r]     = e4m3_1(acc[nb * 4 + 1] + bias0);
                dst[(size_t)n * 32 + r + 8]       = e4m3_1(acc[nb * 4 + 2] + bias8);
                dst[(size_t)(n + 1) * 32 + r + 8] = e4m3_1(acc[nb * 4 + 3] + bias8);
            }
        } else {
            const int c = (blk - 1) * 64 + rl;
            u8* dst  = g_V8 + ((size_t)b * C_ + c) * N_ + n0;
            u8* dst8 = dst + (size_t)8 * N_;
#pragma unroll
            for (int nb = 0; nb < 4; nb++) {
                int n = nwb + nb * 8 + (lane & 3) * 2;
                *(u16*)(dst + n)  = e4m3x2(acc[nb * 4 + 1] + bias0, acc[nb * 4 + 0] + bias0);
                *(u16*)(dst8 + n) = e4m3x2(acc[nb * 4 + 3] + bias8, acc[nb * 4 + 2] + bias8);
            }
        }
        __syncthreads();   // wcur fully consumed before it becomes wnext target
    }
}

// ------------------------- attention device helpers -------------------------
struct AttnCtx {
    u32 sb; int tid, lane, warp, rr, mat, mr, jb, cb;
};

// S = Q'.K'^T (warp: 16q x 128j) -> mma output IS the ex2 argument; e4m3 P write
DEV_INLINE void s_phase(const AttnCtx& cx, char* smem, u32 kbuf, u32 pofs,
                        const u32 aq[4], float& lacc0, float& lacc1)
{
    const int q0 = cx.mr + (cx.lane >> 2);
    const int jl = 2 * (cx.lane & 3);
    const u32 prow0 = pofs + q0 * 256 + ((q0 & 7) << 4);
    const u32 prow8 = prow0 + 8 * 256;
#pragma unroll
    for (int nbp = 0; nbp < 8; nbp++) {
        const int jcol = cx.jb + nbp * 16;
        const int rowB = jcol + ((cx.mat >> 1) << 3) + cx.rr;
        u32 b0, b1, b2, b3;
        ldsm4(b0, b1, b2, b3, kbuf + kswz(rowB, cx.mat & 1));
        float s[8] = {0.f,0.f,0.f,0.f,0.f,0.f,0.f,0.f};
        mmafp8(&s[0], aq, b0, b1);
        mmafp8(&s[4], aq, b2, b3);
        float e0 = ex2f(s[0]), e1 = ex2f(s[1]);
        float e2 = ex2f(s[2]), e3 = ex2f(s[3]);
        float e4 = ex2f(s[4]), e5 = ex2f(s[5]);
        float e6 = ex2f(s[6]), e7 = ex2f(s[7]);
        lacc0 += (e0 + e1) + (e4 + e5);
        lacc1 += (e2 + e3) + (e6 + e7);
        const u32 csw = (u32)(((jcol >> 4) ^ (q0 & 7)) << 4) - (u32)((q0 & 7) << 4);
        *(u16*)(smem + prow0 + csw + jl)     = e4m3x2(e1, e0);
        *(u16*)(smem + prow0 + csw + jl + 8) = e4m3x2(e5, e4);
        *(u16*)(smem + prow8 + csw + jl)     = e4m3x2(e3, e2);
        *(u16*)(smem + prow8 + csw + jl + 8) = e4m3x2(e7, e6);
    }
}

// O += P.V^T (warp: 64q x 32c, K = 256 j)
DEV_INLINE void pv_phase(const AttnCtx& cx, u32 pbuf, u32 vbuf, float pv[64])
{
#pragma unroll
    for (int kk = 0; kk < 8; kk++) {
        u32 ap[4][4];
#pragma unroll
        for (int mt = 0; mt < 4; mt++) {
            const int rowA = mt * 16 + ((cx.mat & 1) << 3) + cx.rr;
            ldsm4(ap[mt][0], ap[mt][1], ap[mt][2], ap[mt][3],
                  pbuf + vswz(rowA, kk * 2 + (cx.mat >> 1)));
        }
#pragma unroll
        for (int np = 0; np < 2; np++) {
            const int rowV = cx.cb + np * 16 + ((cx.mat >> 1) << 3) + cx.rr;
            u32 b0, b1, b2, b3;
            ldsm4(b0, b1, b2, b3, vbuf + vswz(rowV, kk * 2 + (cx.mat & 1)));
#pragma unroll
            for (int mt = 0; mt < 4; mt++) {
                mmafp8(&pv[(mt * 4 + np * 2) * 4],     ap[mt], b0, b1);
                mmafp8(&pv[(mt * 4 + np * 2 + 1) * 4], ap[mt], b2, b3);
            }
        }
    }
}

DEV_INLINE void stage_K(const AttnCtx& cx, u32 kbuf, const u8* Ktb, int j0) {
#pragma unroll
    for (int it = 0; it < 2; it++) {
        int idx = cx.tid + it * 256;
        int row = idx >> 1, c = idx & 1;
        cpa16(kbuf + kswz(row, c), Ktb + (size_t)(j0 + row) * 32 + c * 16);
    }
}
DEV_INLINE void stage_V(const AttnCtx& cx, u32 vbuf, const u8* Vb, int j0) {
#pragma unroll
    for (int it = 0; it < 16; it++) {
        int idx = cx.tid + it * 256;
        int row = idx >> 4, ch = idx & 15;
        cpa16(vbuf + vswz(row, ch), Vb + (size_t)row * N_ + j0 + ch * 16);
    }
}

// ------------------------- attention kernel -------------------------
__global__ __launch_bounds__(256, 2) void attn_kernel(
    const float* __restrict__ x, const float* __restrict__ gamma,
    float* __restrict__ out)
{
    extern __shared__ __align__(1024) char smem[];
    AttnCtx cx;
    cx.sb = smem_u32(smem);
    cx.tid = threadIdx.x;
    cx.lane = cx.tid & 31;
    cx.warp = cx.tid >> 5;
    cx.rr = cx.lane & 7;
    cx.mat = cx.lane >> 3;
    cx.mr = (cx.warp >> 1) * 16;
    cx.jb = (cx.warp & 1) * 128;
    cx.cb = cx.warp * 32;
    const int jh = cx.warp & 1;
    const int i0 = blockIdx.x * BI;
    const int b  = blockIdx.y;

    const u8* Qtb = g_Qt8 + (size_t)b * N_ * 32;
    const u8* Ktb = g_Kt8 + (size_t)b * N_ * 32;
    const u8* Vb  = g_V8  + (size_t)b * C_ * N_;

    {
        if (cx.tid < 128) {
            int row = cx.tid >> 1, c = cx.tid & 1;
            cpa16(cx.sb + SM_Q + kswz(row, c), Qtb + (size_t)(i0 + row) * 32 + c * 16);
        }
        stage_K(cx, cx.sb + SM_K0, Ktb, 0);
        CP_COMMIT();
        stage_V(cx, cx.sb + SM_V, Vb, 0);
        CP_COMMIT();
    }

    float pv[64];
#pragma unroll
    for (int k = 0; k < 64; k++) pv[k] = 0.0f;
    float lacc0 = 0.0f, lacc1 = 0.0f;
    u32 aq[4];

    {
        stage_K(cx, cx.sb + SM_K1, Ktb, BJ);
        CP_COMMIT();
        CP_WAIT(1);
        __syncthreads();
        const int rowA = cx.mr + ((cx.mat & 1) << 3) + cx.rr;
        ldsm4(aq[0], aq[1], aq[2], aq[3], cx.sb + SM_Q + kswz(rowA, cx.mat >> 1));
        s_phase(cx, smem, cx.sb + SM_K0, SM_P0, aq, lacc0, lacc1);
    }

#pragma unroll 1
    for (int t = 1; t < NT; t++) {
        const u32 kcur  = (t & 1) ? cx.sb + SM_K1 : cx.sb + SM_K0;
        const u32 knext = (t & 1) ? cx.sb + SM_K0 : cx.sb + SM_K1;
        const u32 pofs  = (t & 1) ? SM_P1 : SM_P0;
        const u32 pprev = (t & 1) ? cx.sb + SM_P0 : cx.sb + SM_P1;

        if (t < NT - 1) { stage_K(cx, knext, Ktb, (t + 1) * BJ); CP_COMMIT(); CP_WAIT(1); }
        else            { CP_WAIT(0); }
        __syncthreads();

        s_phase(cx, smem, kcur, pofs, aq, lacc0, lacc1);
        pv_phase(cx, pprev, cx.sb + SM_V, pv);
        __syncthreads();

        stage_V(cx, cx.sb + SM_V, Vb, t * BJ);
        CP_COMMIT();
    }

    CP_WAIT(0);
    __syncthreads();
    pv_phase(cx, cx.sb + SM_P1, cx.sb + SM_V, pv);

    lacc0 += __shfl_xor_sync(0xFFFFFFFFu, lacc0, 1);
    lacc0 += __shfl_xor_sync(0xFFFFFFFFu, lacc0, 2);
    lacc1 += __shfl_xor_sync(0xFFFFFFFFu, lacc1, 1);
    lacc1 += __shfl_xor_sync(0xFFFFFFFFu, lacc1, 2);
    __syncthreads();
    if ((cx.lane & 3) == 0) {
        const int q0 = cx.mr + (cx.lane >> 2);
        *(float*)(smem + SM_L + (q0 * 2 + jh) * 4)       = lacc0;
        *(float*)(smem + SM_L + ((q0 + 8) * 2 + jh) * 4) = lacc1;
    }
    __syncthreads();
    if (cx.tid < 64) {
        float s = *(float*)(smem + SM_L + (cx.tid * 2) * 4)
                + *(float*)(smem + SM_L + (cx.tid * 2 + 1) * 4);
        *(float*)(smem + SM_INV + cx.tid * 4) = 1.0f / s;
    }
    __syncthreads();

    const float g = gamma[0];
    const float* xb = x   + ((size_t)b * C_) * N_ + i0;
    float*       ob = out + ((size_t)b * C_) * N_ + i0;

#pragma unroll 1
    for (int qblk = 0; qblk < 4; qblk++) {
        const int mt = qblk;
#pragma unroll
        for (int np = 0; np < 2; np++)
#pragma unroll
            for (int h = 0; h < 2; h++)
#pragma unroll
                for (int e2 = 0; e2 < 2; e2++) {
                    int qloc = (cx.lane >> 2) + e2 * 8;
                    int c = cx.cb + np * 16 + h * 8 + (cx.lane & 3) * 2;
                    float il = *(const float*)(smem + SM_INV + (qblk * 16 + qloc) * 4);
                    float v0 = pv[(mt * 4 + np * 2 + h) * 4 + e2 * 2 + 0];
                    float v1 = pv[(mt * 4 + np * 2 + h) * 4 + e2 * 2 + 1];
                    *(float*)(smem + (c * 17 + qloc) * 4)       = g * v0 * il;
                    *(float*)(smem + ((c + 1) * 17 + qloc) * 4) = g * v1 * il;
                }
        __syncthreads();
#pragma unroll
        for (int i = 0; i < 16; i++) {
            int e = i * 256 + cx.tid;
            int c = e >> 4, q = e & 15;
            int qg = qblk * 16 + q;
            ob[(size_t)c * N_ + qg] = *(const float*)(smem + (c * 17 + q) * 4)
                                    + xb[(size_t)c * N_ + qg];
        }
        __syncthreads();
    }
}

// ------------------------- launch -------------------------
extern "C" void kernel_launch(void* const* d_in, const int* in_sizes, int n_in,
                              void* d_out, int out_size)
{
    (void)in_sizes; (void)n_in; (void)out_size;
    const float* x     = (const float*)d_in[0];
    const float* Wq    = (const float*)d_in[1];
    const float* bq    = (const float*)d_in[2];
    const float* Wk    = (const float*)d_in[3];
    const float* bk    = (const float*)d_in[4];
    const float* Wv    = (const float*)d_in[5];
    const float* bv    = (const float*)d_in[6];
    const float* gamma = (const float*)d_in[7];
    float* out = (float*)d_out;

    cudaFuncSetAttribute(proj2_kernel, cudaFuncAttributeMaxDynamicSharedMemorySize, P2SMEM);
    cudaFuncSetAttribute(attn_kernel, cudaFuncAttributeMaxDynamicSharedMemorySize, SMEM_SZ);

    dim3 blk(256);
    prep_kernel<<<dim3(320), blk>>>(Wq, bq, Wk, bk, Wv, bv);
    proj2_kernel<<<dim3(N_ / 64, B_), blk, P2SMEM>>>(x);
    attn_kernel<<<dim3(N_ / BI, B_), blk, SMEM_SZ>>>(x, gamma, out);
}